// round 12
// baseline (speedup 1.0000x reference)
#include <cuda_runtime.h>
#include <math_constants.h>

// Grid constants (from reference PolarVoxelizer)
#define FOV_HALF 1.134f
#define NUM_A 192
#define NUM_R 320
#define R_MIN 2.7f
#define R_MAX 165.0f
#define Z_DEPTH 100
// Problem shape (fixed per dataset)
#define SEQ 3
#define NPTS 250000
#define NB0 (SEQ * NPTS)          // 750000 batch-0 points (batch 1 never hits the slice)

#define TPB 256
#define NC_BLOCKS ((NB0 + TPB - 1) / TPB)     // 2930 compute blocks
#define TOTAL_BLOCKS (NC_BLOCKS * 8)          // 23440: 1-in-8 compute, 7-in-8 zero

// Scratch: per-point linear index, or -1 if dropped. 3 MB static device array.
__device__ int g_lin[NB0];

// ---------------------------------------------------------------------------
// Fused kernel: blocks with (blockIdx & 7) == 7 compute point indices into
// g_lin; all other blocks zero the output grid. The two block populations are
// co-resident on every SM: zero blocks saturate DRAM writes (tiny issue use),
// compute blocks saturate issue slots (tiny DRAM use). No ordering hazard —
// compute blocks never touch `out`.  (Verified: R7 ran this in ~13us vs
// 16.7+11.5 serial.)
// ---------------------------------------------------------------------------
__global__ void __launch_bounds__(TPB)
pv_fused_kernel(const float* __restrict__ lidars,
                const float* __restrict__ r_bins,
                const float* __restrict__ a_bins,
                float4* __restrict__ out4, int n4,
                float* __restrict__ out, int n_total) {
    int b = blockIdx.x;
    int tid = threadIdx.x;

    if ((b & 7) != 7) {
        // ---------------- zero role ----------------
        int zb = b - (b >> 3);                 // zero-block rank
        int idx = zb * TPB + tid;
        if (idx < n4) out4[idx] = make_float4(0.f, 0.f, 0.f, 0.f);
        if (zb == 0 && tid < 4) {
            int t = (n4 << 2) + tid;
            if (t < n_total) out[t] = 0.f;
        }
        return;
    }

    // ---------------- compute role ----------------
    __shared__ float s_r[NUM_R + 8];
    __shared__ float s_a[NUM_A + 8];
    __shared__ float s_c[4];   // [log2(r0), bins/log2-span, a0, bins/angle-span]

    for (int i = tid; i < NUM_R + 8; i += TPB)
        s_r[i] = (i < NUM_R) ? r_bins[i] : CUDART_INF_F;
    for (int i = tid; i < NUM_A + 8; i += TPB)
        s_a[i] = (i < NUM_A) ? a_bins[i] : CUDART_INF_F;
    __syncthreads();
    if (tid == 0) {
        float l0 = __log2f(s_r[0]);
        s_c[0] = l0;
        s_c[1] = (float)(NUM_R - 1) / (__log2f(s_r[NUM_R - 1]) - l0);
        s_c[2] = s_a[0];
        s_c[3] = (float)(NUM_A - 1) / (s_a[NUM_A - 1] - s_a[0]);
    }
    __syncthreads();

    int i = (b >> 3) * TPB + tid;              // point index 0..NB0-1
    if (i >= NB0) return;

    float x = lidars[3 * i + 0];
    float y = lidars[3 * i + 1];
    float z = lidars[3 * i + 2];

    // Exact same math as the verified-correct kernel (IEEE, no contraction).
    float ang = atan2f(y, x);
    float r2  = __fadd_rn(__fmul_rn(x, x), __fmul_rn(y, y));
    float rad = __fsqrt_rn(r2);

    int lin = -1;
    if ((fabsf(ang) < FOV_HALF) & (rad < R_MAX) & (rad > R_MIN)) {
        // radius bin: log-spaced estimate + 4-wide window count (margin ±1;
        // estimate error ~1e-4 bins; rel_err=0 verified in R7)
        float est_r = (__log2f(rad) - s_c[0]) * s_c[1];
        int k0 = max((int)floorf(est_r) - 1, 0);
        int xg = k0;
        #pragma unroll
        for (int j = 0; j < 4; j++) xg += (s_r[k0 + j] < rad) ? 1 : 0;

        // angle bin: uniform estimate + 4-wide window count
        float est_a = (ang - s_c[2]) * s_c[3];
        int a0 = max((int)floorf(est_a) - 1, 0);
        int yg = a0;
        #pragma unroll
        for (int j = 0; j < 4; j++) yg += (s_a[a0 + j] < ang) ? 1 : 0;

        // z bin (IEEE div to match reference)
        int zg = (int)floorf(__fdiv_rn(__fadd_rn(z, 2.0f), 0.2f));

        if ((unsigned)zg < (unsigned)Z_DEPTH &&
            (unsigned)yg < (unsigned)NUM_A &&
            (unsigned)xg < (unsigned)NUM_R) {
            int s = i / NPTS;
            lin = (((s * Z_DEPTH + zg) * NUM_A) + yg) * NUM_R + xg;
        }
    }
    g_lin[i] = lin;
}

// ---------------------------------------------------------------------------
// Scatter 1.0f at precomputed indices. One point per thread (750k threads)
// for maximum memory-level parallelism: the R7 int4 variant (187k threads)
// was latency-starved at issue=8%, DRAM=12%. __ldcs: g_lin is read once.
// Idempotent stores -> no atomics.
// ---------------------------------------------------------------------------
__global__ void __launch_bounds__(TPB)
pv_scatter_idx_kernel(float* __restrict__ out, int n) {
    int i = blockIdx.x * blockDim.x + threadIdx.x;
    if (i >= n) return;
    int lin = __ldcs(&g_lin[i]);
    if (lin >= 0) out[lin] = 1.0f;
}

// ---------------------------------------------------------------------------
extern "C" void kernel_launch(void* const* d_in, const int* in_sizes, int n_in,
                              void* d_out, int out_size) {
    const float* lidars = (const float*)d_in[0];   // [B,S,N,3] f32
    const float* r_bins = (const float*)d_in[1];   // [320]
    const float* a_bins = (const float*)d_in[2];   // [192]
    float* out = (float*)d_out;                    // [S*Z, A, R] f32 (batch 0 slice)

    int n4 = out_size >> 2;

    pv_fused_kernel<<<TOTAL_BLOCKS, TPB>>>(lidars, r_bins, a_bins,
                                           (float4*)out, n4, out, out_size);

    pv_scatter_idx_kernel<<<(NB0 + TPB - 1) / TPB, TPB>>>(out, NB0);
}